// round 9
// baseline (speedup 1.0000x reference)
#include <cuda_runtime.h>
#include <cstdint>

#define NN 1000000
#define NE 16000000
#define EGRID 1184          // 148 SMs x 8 CTAs: exact full-wave edge grid

// ---- scratch (device globals; no allocations allowed) ----
// g_deg is zero at module load; every call re-zeroes it in k_out's tail,
// so each kernel_launch call sees deg==0 at entry (state invariant).
__device__ int    g_deg[NN];
__device__ float  g_dis[NN];
__device__ float  g_u[NN];
__device__ float  g_acc1[NN];
__device__ float2 g_t[NN];
__device__ float2 g_acc2[NN];

// folded MLP coefficients (valid iff b1 == 0): g(s) = s>0 ? s*Ap : s*Am
__device__ float  g_Ap[2];
__device__ float  g_Am[2];
__device__ int    g_fullpath;   // 1 if any b1[j] != 0 -> exact full MLP path

// ---- no-return global reductions ----
__device__ __forceinline__ void red_add_u32(int* addr) {
    asm volatile("red.global.add.u32 [%0], 1;" :: "l"(addr) : "memory");
}
__device__ __forceinline__ void red_add_f32(float* addr, float v) {
    asm volatile("red.global.add.f32 [%0], %1;" :: "l"(addr), "f"(v) : "memory");
}
__device__ __forceinline__ void red_add_v2(float2* addr, float2 v) {
    asm volatile("red.global.add.v2.f32 [%0], {%1, %2};"
                 :: "l"(addr), "f"(v.x), "f"(v.y) : "memory");
}

// ---------------------------------------------------------------------------
// degree count over target (col) indices; grid-stride, 4 edges/thread/iter.
// Last block (blockIdx.x == EGRID) instead folds the MLP weights into A+/A-.
__global__ __launch_bounds__(256) void k_deg(const int* __restrict__ col, int E,
                                             const float* __restrict__ W1,
                                             const float* __restrict__ b1,
                                             const float* __restrict__ W2) {
    if (blockIdx.x == EGRID) {
        // one-warp weight fold: g(s) = s>0 ? s*Ap : s*Am (requires b1 == 0)
        if (threadIdx.x < 32) {
            int j = threadIdx.x;
            float w  = (j < 16) ? W1[j] : 0.0f;
            float bb = (j < 16) ? b1[j] : 0.0f;
            float w20 = (j < 16) ? W2[2 * j]     : 0.0f;
            float w21 = (j < 16) ? W2[2 * j + 1] : 0.0f;
            float ap0 = (w > 0.0f) ? w * w20 : 0.0f;
            float ap1 = (w > 0.0f) ? w * w21 : 0.0f;
            float am0 = (w < 0.0f) ? w * w20 : 0.0f;
            float am1 = (w < 0.0f) ? w * w21 : 0.0f;
            int   nz  = (bb != 0.0f) ? 1 : 0;
#pragma unroll
            for (int off = 16; off > 0; off >>= 1) {
                ap0 += __shfl_down_sync(0xffffffffu, ap0, off);
                ap1 += __shfl_down_sync(0xffffffffu, ap1, off);
                am0 += __shfl_down_sync(0xffffffffu, am0, off);
                am1 += __shfl_down_sync(0xffffffffu, am1, off);
                nz  += __shfl_down_sync(0xffffffffu, nz,  off);
            }
            if (j == 0) {
                g_Ap[0] = ap0; g_Ap[1] = ap1;
                g_Am[0] = am0; g_Am[1] = am1;
                g_fullpath = nz;
            }
        }
        return;
    }
    const long long stride = (long long)EGRID * 256 * 4;
    for (long long i = ((long long)blockIdx.x * 256 + threadIdx.x) * 4;
         i + 3 < E; i += stride) {
        int4 c = __ldcs(reinterpret_cast<const int4*>(col + i));
        red_add_u32(&g_deg[c.x]);
        red_add_u32(&g_deg[c.y]);
        red_add_u32(&g_deg[c.z]);
        red_add_u32(&g_deg[c.w]);
    }
}

// dis = rsqrt(deg + 1 self-loop); u = dis * x; zero acc1.  4 nodes/thread.
__global__ __launch_bounds__(256) void k_prep(const float4* __restrict__ x4) {
    int i = blockIdx.x * blockDim.x + threadIdx.x;
    if (i >= NN / 4) return;
    int4   dg = reinterpret_cast<const int4*>(g_deg)[i];
    float4 xv = __ldg(&x4[i]);
    float4 d;
    d.x = rsqrtf((float)(dg.x + 1));
    d.y = rsqrtf((float)(dg.y + 1));
    d.z = rsqrtf((float)(dg.z + 1));
    d.w = rsqrtf((float)(dg.w + 1));
    float4 u = make_float4(d.x * xv.x, d.y * xv.y, d.z * xv.z, d.w * xv.w);
    reinterpret_cast<float4*>(g_dis)[i]  = d;
    reinterpret_cast<float4*>(g_u)[i]    = u;
    reinterpret_cast<float4*>(g_acc1)[i] = make_float4(0.f, 0.f, 0.f, 0.f);
}

// scatter layer-1 messages: acc1[col] += u[row]; grid-stride, 4 edges/iter
__global__ __launch_bounds__(256) void k_scat1(const int* __restrict__ row,
                                               const int* __restrict__ col, int E) {
    const long long stride = (long long)EGRID * 256 * 4;
    for (long long i = ((long long)blockIdx.x * 256 + threadIdx.x) * 4;
         i + 3 < E; i += stride) {
        int4 r = __ldcs(reinterpret_cast<const int4*>(row + i));
        int4 c = __ldcs(reinterpret_cast<const int4*>(col + i));
        float u0 = __ldg(&g_u[r.x]);
        float u1 = __ldg(&g_u[r.y]);
        float u2 = __ldg(&g_u[r.z]);
        float u3 = __ldg(&g_u[r.w]);
        red_add_f32(&g_acc1[c.x], u0);
        red_add_f32(&g_acc1[c.y], u1);
        red_add_f32(&g_acc1[c.z], u2);
        red_add_f32(&g_acc1[c.w], u3);
    }
}

// full exact MLP (fallback path, used only if b1 != 0)
__device__ __forceinline__ void mlp_full(float s, const float4* W1,
                                         const float4* b1, const float4* W2,
                                         float& g0, float& g1) {
    g0 = 0.0f; g1 = 0.0f;
#pragma unroll
    for (int q = 0; q < 4; q++) {
        float4 w1 = __ldg(&W1[q]);
        float4 bb = __ldg(&b1[q]);
        float4 e0 = __ldg(&W2[2 * q]);
        float4 e1 = __ldg(&W2[2 * q + 1]);
        float h0 = fmaxf(fmaf(s, w1.x, bb.x), 0.0f);
        float h1 = fmaxf(fmaf(s, w1.y, bb.y), 0.0f);
        float h2 = fmaxf(fmaf(s, w1.z, bb.z), 0.0f);
        float h3 = fmaxf(fmaf(s, w1.w, bb.w), 0.0f);
        g0 = fmaf(h0, e0.x, g0); g1 = fmaf(h0, e0.y, g1);
        g0 = fmaf(h1, e0.z, g0); g1 = fmaf(h1, e0.w, g1);
        g0 = fmaf(h2, e1.x, g0); g1 = fmaf(h2, e1.y, g1);
        g0 = fmaf(h3, e1.z, g0); g1 = fmaf(h3, e1.w, g1);
    }
}

// per-node layer-2 input: t = dis * g(dis*(acc1+u)); zero acc2. 4 nodes/thread.
__global__ __launch_bounds__(256) void k_node2(const float4* __restrict__ W1,
                                               const float4* __restrict__ b1,
                                               const float4* __restrict__ W2) {
    int i = blockIdx.x * blockDim.x + threadIdx.x;
    if (i >= NN / 4) return;
    float4 d  = reinterpret_cast<const float4*>(g_dis)[i];
    float4 a  = reinterpret_cast<const float4*>(g_acc1)[i];
    float4 uu = reinterpret_cast<const float4*>(g_u)[i];
    float s0 = d.x * (a.x + uu.x);
    float s1 = d.y * (a.y + uu.y);
    float s2 = d.z * (a.z + uu.z);
    float s3 = d.w * (a.w + uu.w);
    float p0, p1, q0, q1, r0, r1, v0, v1;
    if (g_fullpath == 0) {
        float ap0 = g_Ap[0], ap1 = g_Ap[1];
        float am0 = g_Am[0], am1 = g_Am[1];
        p0 = s0 * (s0 > 0.0f ? ap0 : am0);  p1 = s0 * (s0 > 0.0f ? ap1 : am1);
        q0 = s1 * (s1 > 0.0f ? ap0 : am0);  q1 = s1 * (s1 > 0.0f ? ap1 : am1);
        r0 = s2 * (s2 > 0.0f ? ap0 : am0);  r1 = s2 * (s2 > 0.0f ? ap1 : am1);
        v0 = s3 * (s3 > 0.0f ? ap0 : am0);  v1 = s3 * (s3 > 0.0f ? ap1 : am1);
    } else {
        mlp_full(s0, W1, b1, W2, p0, p1);
        mlp_full(s1, W1, b1, W2, q0, q1);
        mlp_full(s2, W1, b1, W2, r0, r1);
        mlp_full(s3, W1, b1, W2, v0, v1);
    }
    float4* t4 = reinterpret_cast<float4*>(g_t);
    t4[2 * i]     = make_float4(d.x * p0, d.x * p1, d.y * q0, d.y * q1);
    t4[2 * i + 1] = make_float4(d.z * r0, d.z * r1, d.w * v0, d.w * v1);
    float4* z4 = reinterpret_cast<float4*>(g_acc2);
    z4[2 * i]     = make_float4(0.f, 0.f, 0.f, 0.f);
    z4[2 * i + 1] = make_float4(0.f, 0.f, 0.f, 0.f);
}

// scatter layer-2 messages: acc2[col] += t[row]; grid-stride, 4 edges/iter
__global__ __launch_bounds__(256) void k_scat2(const int* __restrict__ row,
                                               const int* __restrict__ col, int E) {
    const long long stride = (long long)EGRID * 256 * 4;
    for (long long i = ((long long)blockIdx.x * 256 + threadIdx.x) * 4;
         i + 3 < E; i += stride) {
        int4 r = __ldcs(reinterpret_cast<const int4*>(row + i));
        int4 c = __ldcs(reinterpret_cast<const int4*>(col + i));
        float2 t0 = __ldg(&g_t[r.x]);
        float2 t1 = __ldg(&g_t[r.y]);
        float2 t2 = __ldg(&g_t[r.z]);
        float2 t3 = __ldg(&g_t[r.w]);
        red_add_v2(&g_acc2[c.x], t0);
        red_add_v2(&g_acc2[c.y], t1);
        red_add_v2(&g_acc2[c.z], t2);
        red_add_v2(&g_acc2[c.w], t3);
    }
}

// final: out = dis*(acc2 + t) + b2, log_softmax over 2 classes; 2 nodes/thread.
// Also re-zeroes g_deg for the next call (graph replay invariant).
__global__ __launch_bounds__(256) void k_out(const float* __restrict__ b2,
                                             float4* __restrict__ out) {
    int i = blockIdx.x * blockDim.x + threadIdx.x;
    if (i >= NN / 2) return;
    float b20 = __ldg(&b2[0]);
    float b21 = __ldg(&b2[1]);
    float2 d = reinterpret_cast<const float2*>(g_dis)[i];
    float4 a = reinterpret_cast<const float4*>(g_acc2)[i];
    float4 t = reinterpret_cast<const float4*>(g_t)[i];
    float o0 = fmaf(d.x, a.x + t.x, b20);
    float o1 = fmaf(d.x, a.y + t.y, b21);
    float o2 = fmaf(d.y, a.z + t.z, b20);
    float o3 = fmaf(d.y, a.w + t.w, b21);
    float m0  = fmaxf(o0, o1);
    float l0  = m0 + log1pf(__expf(fminf(o0, o1) - m0));
    float m1  = fmaxf(o2, o3);
    float l1  = m1 + log1pf(__expf(fminf(o2, o3) - m1));
    out[i] = make_float4(o0 - l0, o1 - l0, o2 - l1, o3 - l1);
    // restore deg=0 for the next replay (2 nodes per thread)
    reinterpret_cast<int2*>(g_deg)[i] = make_int2(0, 0);
}

// ---------------------------------------------------------------------------
extern "C" void kernel_launch(void* const* d_in, const int* in_sizes, int n_in,
                              void* d_out, int out_size) {
    const float* x   = (const float*)d_in[0];
    const int*   ei  = (const int*)d_in[1];
    const float* W1  = (const float*)d_in[2];
    const float* b1  = (const float*)d_in[3];
    const float* W2  = (const float*)d_in[4];
    const float* b2  = (const float*)d_in[5];

    const int E = in_sizes[1] / 2;      // edge_index is [2, E]
    const int* row = ei;                // source
    const int* col = ei + E;            // target

    const int TB = 256;
    const int n4Blocks = (NN / 4 + TB - 1) / TB;
    const int n2Blocks = (NN / 2 + TB - 1) / TB;

    k_deg  <<<EGRID + 1, TB>>>(col, E, W1, b1, W2);   // +1 block folds weights
    k_prep <<<n4Blocks, TB>>>((const float4*)x);
    k_scat1<<<EGRID, TB>>>(row, col, E);
    k_node2<<<n4Blocks, TB>>>((const float4*)W1, (const float4*)b1,
                              (const float4*)W2);
    k_scat2<<<EGRID, TB>>>(row, col, E);
    k_out  <<<n2Blocks, TB>>>(b2, (float4*)d_out);
}

// round 10
// speedup vs baseline: 1.1313x; 1.1313x over previous
#include <cuda_runtime.h>
#include <cstdint>

#define NN 1000000
#define NE 16000000

// ---- scratch (device globals; no allocations allowed) ----
// g_deg is zero at module load; every call re-zeroes it in k_out's tail,
// so each kernel_launch call sees deg==0 at entry (state invariant).
__device__ int    g_deg[NN];
__device__ float  g_dis[NN];
__device__ float  g_u[NN];
__device__ float  g_acc1[NN];
__device__ float2 g_t[NN];
__device__ float2 g_acc2[NN];

// ---- no-return global reductions ----
__device__ __forceinline__ void red_add_u32(int* addr) {
    asm volatile("red.global.add.u32 [%0], 1;" :: "l"(addr) : "memory");
}
__device__ __forceinline__ void red_add_f32(float* addr, float v) {
    asm volatile("red.global.add.f32 [%0], %1;" :: "l"(addr), "f"(v) : "memory");
}
__device__ __forceinline__ void red_add_v2(float2* addr, float2 v) {
    asm volatile("red.global.add.v2.f32 [%0], {%1, %2};"
                 :: "l"(addr), "f"(v.x), "f"(v.y) : "memory");
}

// ---------------------------------------------------------------------------
// degree count over target (col) indices; 4 edges per thread
__global__ __launch_bounds__(256) void k_deg(const int* __restrict__ col, int E) {
    int i = (blockIdx.x * blockDim.x + threadIdx.x) * 4;
    if (i + 3 < E) {
        int4 c = __ldcs(reinterpret_cast<const int4*>(col + i));
        red_add_u32(&g_deg[c.x]);
        red_add_u32(&g_deg[c.y]);
        red_add_u32(&g_deg[c.z]);
        red_add_u32(&g_deg[c.w]);
    }
}

// dis = rsqrt(deg + 1 self-loop); u = dis * x; zero acc1.  4 nodes/thread.
__global__ __launch_bounds__(256) void k_prep(const float4* __restrict__ x4) {
    int i = blockIdx.x * blockDim.x + threadIdx.x;
    if (i >= NN / 4) return;
    int4   dg = reinterpret_cast<const int4*>(g_deg)[i];
    float4 xv = __ldg(&x4[i]);
    float4 d;
    d.x = rsqrtf((float)(dg.x + 1));
    d.y = rsqrtf((float)(dg.y + 1));
    d.z = rsqrtf((float)(dg.z + 1));
    d.w = rsqrtf((float)(dg.w + 1));
    float4 u = make_float4(d.x * xv.x, d.y * xv.y, d.z * xv.z, d.w * xv.w);
    reinterpret_cast<float4*>(g_dis)[i]  = d;
    reinterpret_cast<float4*>(g_u)[i]    = u;
    reinterpret_cast<float4*>(g_acc1)[i] = make_float4(0.f, 0.f, 0.f, 0.f);
}

// scatter layer-1 messages: acc1[col] += u[row]; 4 edges per thread
__global__ __launch_bounds__(256) void k_scat1(const int* __restrict__ row,
                                               const int* __restrict__ col, int E) {
    int i = (blockIdx.x * blockDim.x + threadIdx.x) * 4;
    if (i + 3 < E) {
        int4 r = __ldcs(reinterpret_cast<const int4*>(row + i));
        int4 c = __ldcs(reinterpret_cast<const int4*>(col + i));
        float u0 = __ldg(&g_u[r.x]);
        float u1 = __ldg(&g_u[r.y]);
        float u2 = __ldg(&g_u[r.z]);
        float u3 = __ldg(&g_u[r.w]);
        red_add_f32(&g_acc1[c.x], u0);
        red_add_f32(&g_acc1[c.y], u1);
        red_add_f32(&g_acc1[c.z], u2);
        red_add_f32(&g_acc1[c.w], u3);
    }
}

// per-node MLP, 2 nodes/thread: s -> relu(W1*s+b1) -> @W2 ; t = dis*g; zero acc2
__device__ __forceinline__ void mlp2(float s, const float4* w1q, const float4* bbq,
                                     const float4* e0q, const float4* e1q,
                                     float& g0, float& g1) {
    g0 = 0.0f; g1 = 0.0f;
#pragma unroll
    for (int q = 0; q < 4; q++) {
        float h0 = fmaxf(fmaf(s, w1q[q].x, bbq[q].x), 0.0f);
        float h1 = fmaxf(fmaf(s, w1q[q].y, bbq[q].y), 0.0f);
        float h2 = fmaxf(fmaf(s, w1q[q].z, bbq[q].z), 0.0f);
        float h3 = fmaxf(fmaf(s, w1q[q].w, bbq[q].w), 0.0f);
        g0 = fmaf(h0, e0q[q].x, g0); g1 = fmaf(h0, e0q[q].y, g1);
        g0 = fmaf(h1, e0q[q].z, g0); g1 = fmaf(h1, e0q[q].w, g1);
        g0 = fmaf(h2, e1q[q].x, g0); g1 = fmaf(h2, e1q[q].y, g1);
        g0 = fmaf(h3, e1q[q].z, g0); g1 = fmaf(h3, e1q[q].w, g1);
    }
}

__global__ __launch_bounds__(256) void k_node2(const float4* __restrict__ W1,
                                               const float4* __restrict__ b1,
                                               const float4* __restrict__ W2) {
    int i = blockIdx.x * blockDim.x + threadIdx.x;
    if (i >= NN / 2) return;
    float4 w1q[4], bbq[4], e0q[4], e1q[4];
#pragma unroll
    for (int q = 0; q < 4; q++) {
        w1q[q] = __ldg(&W1[q]);
        bbq[q] = __ldg(&b1[q]);
        e0q[q] = __ldg(&W2[2 * q]);
        e1q[q] = __ldg(&W2[2 * q + 1]);
    }
    float2 d  = reinterpret_cast<const float2*>(g_dis)[i];
    float2 a  = reinterpret_cast<const float2*>(g_acc1)[i];
    float2 uu = reinterpret_cast<const float2*>(g_u)[i];
    float s0 = d.x * (a.x + uu.x);
    float s1 = d.y * (a.y + uu.y);
    float p0, p1, q0, q1;
    mlp2(s0, w1q, bbq, e0q, e1q, p0, p1);
    mlp2(s1, w1q, bbq, e0q, e1q, q0, q1);
    reinterpret_cast<float4*>(g_t)[i] =
        make_float4(d.x * p0, d.x * p1, d.y * q0, d.y * q1);
    reinterpret_cast<float4*>(g_acc2)[i] = make_float4(0.f, 0.f, 0.f, 0.f);
}

// scatter layer-2 messages: acc2[col] += t[row]; 4 edges per thread
__global__ __launch_bounds__(256) void k_scat2(const int* __restrict__ row,
                                               const int* __restrict__ col, int E) {
    int i = (blockIdx.x * blockDim.x + threadIdx.x) * 4;
    if (i + 3 < E) {
        int4 r = __ldcs(reinterpret_cast<const int4*>(row + i));
        int4 c = __ldcs(reinterpret_cast<const int4*>(col + i));
        float2 t0 = __ldg(&g_t[r.x]);
        float2 t1 = __ldg(&g_t[r.y]);
        float2 t2 = __ldg(&g_t[r.z]);
        float2 t3 = __ldg(&g_t[r.w]);
        red_add_v2(&g_acc2[c.x], t0);
        red_add_v2(&g_acc2[c.y], t1);
        red_add_v2(&g_acc2[c.z], t2);
        red_add_v2(&g_acc2[c.w], t3);
    }
}

// final: out = dis*(acc2 + t) + b2, log_softmax over 2 classes; 2 nodes/thread.
// Also re-zeroes g_deg for the next call (graph replay invariant).
__global__ __launch_bounds__(256) void k_out(const float* __restrict__ b2,
                                             float4* __restrict__ out) {
    int i = blockIdx.x * blockDim.x + threadIdx.x;
    if (i >= NN / 2) return;
    float b20 = __ldg(&b2[0]);
    float b21 = __ldg(&b2[1]);
    float2 d = reinterpret_cast<const float2*>(g_dis)[i];
    float4 a = reinterpret_cast<const float4*>(g_acc2)[i];
    float4 t = reinterpret_cast<const float4*>(g_t)[i];
    float o0 = fmaf(d.x, a.x + t.x, b20);
    float o1 = fmaf(d.x, a.y + t.y, b21);
    float o2 = fmaf(d.y, a.z + t.z, b20);
    float o3 = fmaf(d.y, a.w + t.w, b21);
    float m0  = fmaxf(o0, o1);
    float l0  = m0 + log1pf(__expf(fminf(o0, o1) - m0));
    float m1  = fmaxf(o2, o3);
    float l1  = m1 + log1pf(__expf(fminf(o2, o3) - m1));
    out[i] = make_float4(o0 - l0, o1 - l0, o2 - l1, o3 - l1);
    // restore deg=0 for the next replay (2 nodes per thread)
    reinterpret_cast<int2*>(g_deg)[i] = make_int2(0, 0);
}

// ---------------------------------------------------------------------------
extern "C" void kernel_launch(void* const* d_in, const int* in_sizes, int n_in,
                              void* d_out, int out_size) {
    const float* x   = (const float*)d_in[0];
    const int*   ei  = (const int*)d_in[1];
    const float* W1  = (const float*)d_in[2];
    const float* b1  = (const float*)d_in[3];
    const float* W2  = (const float*)d_in[4];
    const float* b2  = (const float*)d_in[5];

    const int E = in_sizes[1] / 2;      // edge_index is [2, E]
    const int* row = ei;                // source
    const int* col = ei + E;            // target

    const int TB = 256;
    const int n4Blocks = (NN / 4 + TB - 1) / TB;
    const int n2Blocks = (NN / 2 + TB - 1) / TB;
    const int edgeBlocks = (E / 4 + TB - 1) / TB;   // 4 edges per thread

    k_deg  <<<edgeBlocks, TB>>>(col, E);
    k_prep <<<n4Blocks, TB>>>((const float4*)x);
    k_scat1<<<edgeBlocks, TB>>>(row, col, E);
    k_node2<<<n2Blocks, TB>>>((const float4*)W1, (const float4*)b1,
                              (const float4*)W2);
    k_scat2<<<edgeBlocks, TB>>>(row, col, E);
    k_out  <<<n2Blocks, TB>>>(b2, (float4*)d_out);
}

// round 11
// speedup vs baseline: 1.1472x; 1.0140x over previous
#include <cuda_runtime.h>
#include <cstdint>

#define NN 1000000
#define NE 16000000

// ---- scratch (device globals; no allocations allowed) ----
// g_deg is zero at module load; every call re-zeroes it in k_out's tail,
// so each kernel_launch call sees deg==0 at entry (state invariant).
__device__ int    g_deg[NN];
__device__ float  g_u[NN];
__device__ float  g_acc1[NN];
__device__ float2 g_t[NN];
__device__ float2 g_acc2[NN];

// folded MLP coefficients (valid iff b1 == 0): g(s) = s>0 ? s*Ap : s*Am
__device__ float  g_Ap[2];
__device__ float  g_Am[2];
__device__ int    g_fullpath;   // nonzero if any b1[j] != 0 -> exact full MLP

// ---- no-return global reductions ----
__device__ __forceinline__ void red_add_u32(int* addr) {
    asm volatile("red.global.add.u32 [%0], 1;" :: "l"(addr) : "memory");
}
__device__ __forceinline__ void red_add_f32(float* addr, float v) {
    asm volatile("red.global.add.f32 [%0], %1;" :: "l"(addr), "f"(v) : "memory");
}
__device__ __forceinline__ void red_add_v2(float2* addr, float2 v) {
    asm volatile("red.global.add.v2.f32 [%0], {%1, %2};"
                 :: "l"(addr), "f"(v.x), "f"(v.y) : "memory");
}

// ---------------------------------------------------------------------------
// degree count over target (col) indices; 4 edges per thread (flat mapping)
__global__ __launch_bounds__(256) void k_deg(const int* __restrict__ col, int E) {
    int i = (blockIdx.x * blockDim.x + threadIdx.x) * 4;
    if (i + 3 < E) {
        int4 c = __ldcs(reinterpret_cast<const int4*>(col + i));
        red_add_u32(&g_deg[c.x]);
        red_add_u32(&g_deg[c.y]);
        red_add_u32(&g_deg[c.z]);
        red_add_u32(&g_deg[c.w]);
    }
}

// u = rsqrt(deg+1) * x; zero acc1. 4 nodes/thread, flat mapping.
// Extra block (blockIdx.x == gridDim.x-1) folds MLP weights into A+/A-.
__global__ __launch_bounds__(256) void k_prep(const float4* __restrict__ x4,
                                              const float* __restrict__ W1,
                                              const float* __restrict__ b1,
                                              const float* __restrict__ W2) {
    if (blockIdx.x == gridDim.x - 1) {
        if (threadIdx.x < 32) {
            int j = threadIdx.x;
            float w   = (j < 16) ? W1[j] : 0.0f;
            float bb  = (j < 16) ? b1[j] : 0.0f;
            float w20 = (j < 16) ? W2[2 * j]     : 0.0f;
            float w21 = (j < 16) ? W2[2 * j + 1] : 0.0f;
            float ap0 = (w > 0.0f) ? w * w20 : 0.0f;
            float ap1 = (w > 0.0f) ? w * w21 : 0.0f;
            float am0 = (w < 0.0f) ? w * w20 : 0.0f;
            float am1 = (w < 0.0f) ? w * w21 : 0.0f;
            int   nz  = (bb != 0.0f) ? 1 : 0;
#pragma unroll
            for (int off = 16; off > 0; off >>= 1) {
                ap0 += __shfl_down_sync(0xffffffffu, ap0, off);
                ap1 += __shfl_down_sync(0xffffffffu, ap1, off);
                am0 += __shfl_down_sync(0xffffffffu, am0, off);
                am1 += __shfl_down_sync(0xffffffffu, am1, off);
                nz  += __shfl_down_sync(0xffffffffu, nz,  off);
            }
            if (j == 0) {
                g_Ap[0] = ap0; g_Ap[1] = ap1;
                g_Am[0] = am0; g_Am[1] = am1;
                g_fullpath = nz;
            }
        }
        return;
    }
    int i = blockIdx.x * blockDim.x + threadIdx.x;
    if (i >= NN / 4) return;
    int4   dg = reinterpret_cast<const int4*>(g_deg)[i];
    float4 xv = __ldg(&x4[i]);
    float4 u;
    u.x = rsqrtf((float)(dg.x + 1)) * xv.x;
    u.y = rsqrtf((float)(dg.y + 1)) * xv.y;
    u.z = rsqrtf((float)(dg.z + 1)) * xv.z;
    u.w = rsqrtf((float)(dg.w + 1)) * xv.w;
    reinterpret_cast<float4*>(g_u)[i]    = u;
    reinterpret_cast<float4*>(g_acc1)[i] = make_float4(0.f, 0.f, 0.f, 0.f);
}

// scatter layer-1 messages: acc1[col] += u[row]; 4 edges per thread
__global__ __launch_bounds__(256) void k_scat1(const int* __restrict__ row,
                                               const int* __restrict__ col, int E) {
    int i = (blockIdx.x * blockDim.x + threadIdx.x) * 4;
    if (i + 3 < E) {
        int4 r = __ldcs(reinterpret_cast<const int4*>(row + i));
        int4 c = __ldcs(reinterpret_cast<const int4*>(col + i));
        float u0 = __ldg(&g_u[r.x]);
        float u1 = __ldg(&g_u[r.y]);
        float u2 = __ldg(&g_u[r.z]);
        float u3 = __ldg(&g_u[r.w]);
        red_add_f32(&g_acc1[c.x], u0);
        red_add_f32(&g_acc1[c.y], u1);
        red_add_f32(&g_acc1[c.z], u2);
        red_add_f32(&g_acc1[c.w], u3);
    }
}

// full exact MLP (fallback path, used only if b1 != 0)
__device__ __noinline__ void mlp_full(float s, const float4* W1,
                                      const float4* b1, const float4* W2,
                                      float& g0, float& g1) {
    g0 = 0.0f; g1 = 0.0f;
#pragma unroll
    for (int q = 0; q < 4; q++) {
        float4 w1 = __ldg(&W1[q]);
        float4 bb = __ldg(&b1[q]);
        float4 e0 = __ldg(&W2[2 * q]);
        float4 e1 = __ldg(&W2[2 * q + 1]);
        float h0 = fmaxf(fmaf(s, w1.x, bb.x), 0.0f);
        float h1 = fmaxf(fmaf(s, w1.y, bb.y), 0.0f);
        float h2 = fmaxf(fmaf(s, w1.z, bb.z), 0.0f);
        float h3 = fmaxf(fmaf(s, w1.w, bb.w), 0.0f);
        g0 = fmaf(h0, e0.x, g0); g1 = fmaf(h0, e0.y, g1);
        g0 = fmaf(h1, e0.z, g0); g1 = fmaf(h1, e0.w, g1);
        g0 = fmaf(h2, e1.x, g0); g1 = fmaf(h2, e1.y, g1);
        g0 = fmaf(h3, e1.z, g0); g1 = fmaf(h3, e1.w, g1);
    }
}

// per-node layer-2 input: t = d * g(d*(acc1+u)), d = rsqrt(deg+1); zero acc2.
// 2 nodes/thread, flat mapping.
__global__ __launch_bounds__(256) void k_node2(const float4* __restrict__ W1,
                                               const float4* __restrict__ b1,
                                               const float4* __restrict__ W2) {
    int i = blockIdx.x * blockDim.x + threadIdx.x;
    if (i >= NN / 2) return;
    int2   dg = reinterpret_cast<const int2*>(g_deg)[i];
    float2 a  = reinterpret_cast<const float2*>(g_acc1)[i];
    float2 uu = reinterpret_cast<const float2*>(g_u)[i];
    float d0 = rsqrtf((float)(dg.x + 1));
    float d1 = rsqrtf((float)(dg.y + 1));
    float s0 = d0 * (a.x + uu.x);
    float s1 = d1 * (a.y + uu.y);
    float p0, p1, q0, q1;
    if (g_fullpath == 0) {
        float ap0 = g_Ap[0], ap1 = g_Ap[1];
        float am0 = g_Am[0], am1 = g_Am[1];
        p0 = s0 * (s0 > 0.0f ? ap0 : am0);  p1 = s0 * (s0 > 0.0f ? ap1 : am1);
        q0 = s1 * (s1 > 0.0f ? ap0 : am0);  q1 = s1 * (s1 > 0.0f ? ap1 : am1);
    } else {
        mlp_full(s0, W1, b1, W2, p0, p1);
        mlp_full(s1, W1, b1, W2, q0, q1);
    }
    reinterpret_cast<float4*>(g_t)[i] =
        make_float4(d0 * p0, d0 * p1, d1 * q0, d1 * q1);
    reinterpret_cast<float4*>(g_acc2)[i] = make_float4(0.f, 0.f, 0.f, 0.f);
}

// scatter layer-2 messages: acc2[col] += t[row]; 4 edges per thread
__global__ __launch_bounds__(256) void k_scat2(const int* __restrict__ row,
                                               const int* __restrict__ col, int E) {
    int i = (blockIdx.x * blockDim.x + threadIdx.x) * 4;
    if (i + 3 < E) {
        int4 r = __ldcs(reinterpret_cast<const int4*>(row + i));
        int4 c = __ldcs(reinterpret_cast<const int4*>(col + i));
        float2 t0 = __ldg(&g_t[r.x]);
        float2 t1 = __ldg(&g_t[r.y]);
        float2 t2 = __ldg(&g_t[r.z]);
        float2 t3 = __ldg(&g_t[r.w]);
        red_add_v2(&g_acc2[c.x], t0);
        red_add_v2(&g_acc2[c.y], t1);
        red_add_v2(&g_acc2[c.z], t2);
        red_add_v2(&g_acc2[c.w], t3);
    }
}

// final: out = d*(acc2 + t) + b2 (d = rsqrt(deg+1)), log_softmax over 2 classes;
// 2 nodes/thread. Re-zeroes g_deg after reading (graph replay invariant).
__global__ __launch_bounds__(256) void k_out(const float* __restrict__ b2,
                                             float4* __restrict__ out) {
    int i = blockIdx.x * blockDim.x + threadIdx.x;
    if (i >= NN / 2) return;
    float b20 = __ldg(&b2[0]);
    float b21 = __ldg(&b2[1]);
    int2   dg = reinterpret_cast<const int2*>(g_deg)[i];
    float4 a  = reinterpret_cast<const float4*>(g_acc2)[i];
    float4 t  = reinterpret_cast<const float4*>(g_t)[i];
    float d0 = rsqrtf((float)(dg.x + 1));
    float d1 = rsqrtf((float)(dg.y + 1));
    float o0 = fmaf(d0, a.x + t.x, b20);
    float o1 = fmaf(d0, a.y + t.y, b21);
    float o2 = fmaf(d1, a.z + t.z, b20);
    float o3 = fmaf(d1, a.w + t.w, b21);
    float m0  = fmaxf(o0, o1);
    float l0  = m0 + log1pf(__expf(fminf(o0, o1) - m0));
    float m1  = fmaxf(o2, o3);
    float l1  = m1 + log1pf(__expf(fminf(o2, o3) - m1));
    out[i] = make_float4(o0 - l0, o1 - l0, o2 - l1, o3 - l1);
    // restore deg=0 for the next replay (2 nodes per thread)
    reinterpret_cast<int2*>(g_deg)[i] = make_int2(0, 0);
}

// ---------------------------------------------------------------------------
extern "C" void kernel_launch(void* const* d_in, const int* in_sizes, int n_in,
                              void* d_out, int out_size) {
    const float* x   = (const float*)d_in[0];
    const int*   ei  = (const int*)d_in[1];
    const float* W1  = (const float*)d_in[2];
    const float* b1  = (const float*)d_in[3];
    const float* W2  = (const float*)d_in[4];
    const float* b2  = (const float*)d_in[5];

    const int E = in_sizes[1] / 2;      // edge_index is [2, E]
    const int* row = ei;                // source
    const int* col = ei + E;            // target

    const int TB = 256;
    const int n4Blocks = (NN / 4 + TB - 1) / TB;
    const int n2Blocks = (NN / 2 + TB - 1) / TB;
    const int edgeBlocks = (E / 4 + TB - 1) / TB;   // 4 edges per thread

    k_deg  <<<edgeBlocks, TB>>>(col, E);
    k_prep <<<n4Blocks + 1, TB>>>((const float4*)x, W1, b1, W2); // +1: weight fold
    k_scat1<<<edgeBlocks, TB>>>(row, col, E);
    k_node2<<<n2Blocks, TB>>>((const float4*)W1, (const float4*)b1,
                              (const float4*)W2);
    k_scat2<<<edgeBlocks, TB>>>(row, col, E);
    k_out  <<<n2Blocks, TB>>>(b2, (float4*)d_out);
}